// round 15
// baseline (speedup 1.0000x reference)
#include <cuda_runtime.h>
#include <math.h>

#define NPTS   131072
#define BATCH  8
#define VIEWS  2
#define HH     1024
#define WW     1024
#define NPIX   (VIEWS * BATCH * HH * WW)   // 16777216
#define FUSED_ELEMS NPIX

#define PT_BLOCKS   (NPTS / 256)           // 512
#define CP_BLOCKS   4096                   // each thread copies 4 float4
#define CP_THREADS  (CP_BLOCKS * 256)      // 1048576
#define TOT_BLOCKS  (PT_BLOCKS + CP_BLOCKS)  // 4608 = 512 * 9

// ---------------- scratch (device globals only; no allocation allowed) ------
__device__ unsigned int g_near[BATCH * VIEWS] = {
    0x7f800000u,0x7f800000u,0x7f800000u,0x7f800000u,
    0x7f800000u,0x7f800000u,0x7f800000u,0x7f800000u,
    0x7f800000u,0x7f800000u,0x7f800000u,0x7f800000u,
    0x7f800000u,0x7f800000u,0x7f800000u,0x7f800000u};
__device__ unsigned int g_far[BATCH * VIEWS]  = {0};
__device__ int          g_has[BATCH]          = {0};
// Self-cleaning winner map: 0 == clean (zero-init at load; scatter_final_k
// re-zeroes exactly the entries each replay dirties). Key = point index n + 1;
// contenders at a pixel have distinct n, so atomicMax picks the reference's
// last-write-wins point deterministically.
__device__ unsigned int g_winner[NPIX];             // 64 MB
__device__ float        g_val[NPTS * 2];
__device__ int          g_pix[NPTS * 2];

// ---------------- Jacobi rotation on 4x4 symmetric, fixed (P,Q) -------------
// Executed path: EXACT IEEE sequence (best-known accuracy, rel_err 7.945e-4).
// Relative skip threshold (eps*trace) — converged rotations skip instead of
// burning MUFU on rounding noise.
template <int P, int Q>
__device__ __forceinline__ void jrot(float M[4][4], float Vv[4][4], float thr)
{
    float apq = M[P][Q];
    if (fabsf(apq) < thr) return;
    float app = M[P][P], aqq = M[Q][Q];
    float tau = (aqq - app) / (2.0f * apq);
    float t = copysignf(1.0f, tau) / (fabsf(tau) + sqrtf(1.0f + tau * tau));
    float c = 1.0f / sqrtf(1.0f + t * t);
    float s = t * c;
    M[P][P] = app - t * apq;
    M[Q][Q] = aqq + t * apq;
    M[P][Q] = 0.0f; M[Q][P] = 0.0f;
#pragma unroll
    for (int k = 0; k < 4; k++) {
        if (k == P || k == Q) continue;
        float mkp = M[k][P], mkq = M[k][Q];
        float np = c * mkp - s * mkq;
        float nq = s * mkp + c * mkq;
        M[k][P] = np; M[P][k] = np;
        M[k][Q] = nq; M[Q][k] = nq;
    }
#pragma unroll
    for (int k = 0; k < 4; k++) {
        float vkp = Vv[k][P], vkq = Vv[k][Q];
        Vv[k][P] = c * vkp - s * vkq;
        Vv[k][Q] = s * vkp + c * vkq;
    }
}

// ---------------- K1 (fused): interleaved copy + point blocks ----------------
// Roles INTERLEAVED (every 9th block = point): with point blocks packed at
// blockIdx 0-511, wave 1 (~500 blocks) was all-point — the chip ran
// latency-bound SVD first and the DRAM-bound copy serialized behind it
// (observed 3.0 TB/s vs 4.7 standalone). Interleaving mixes 8 copy : 1 point
// per wave so the copy saturates DRAM while point compute hides under it.
__global__ void fused_k(const float* __restrict__ mk0,
                        const float* __restrict__ mk1,
                        const float* __restrict__ conf,
                        const int*   __restrict__ bids,
                        const float* __restrict__ intr,
                        const float* __restrict__ extr,
                        const float* __restrict__ disps,
                        float*       __restrict__ out)
{
    int grp = blockIdx.x / 9;
    int rem = blockIdx.x % 9;
    if (rem != 8) {
        // ---- copy path (copy block index = grp*8 + rem) ----
        const float4* in4  = (const float4*)disps;
        float4*       out4 = (float4*)out;
        int i = (grp * 8 + rem) * blockDim.x + threadIdx.x;
#pragma unroll
        for (int j = 0; j < 4; j++)
            out4[i + j * CP_THREADS] = in4[i + j * CP_THREADS];
        return;
    }

    // ---- per-block setup: 16 (b,v) projection matrices into SMEM ----
    __shared__ float s_proj[BATCH * VIEWS][12];
    __shared__ float s_row2[BATCH * VIEWS][4];
    if (threadIdx.x < BATCH * VIEWS) {
        int i = threadIdx.x;
        // extrinsics are rigid: E = [R t; 0 0 0 1]  =>  inv = [R^T, -R^T t; 0 1]
        double R[3][3], t[3];
        for (int r = 0; r < 3; r++) {
            for (int c = 0; c < 3; c++) R[r][c] = (double)extr[i * 16 + r * 4 + c];
            t[r] = (double)extr[i * 16 + r * 4 + 3];
        }
        double inv[3][4];
        for (int r = 0; r < 3; r++) {
            inv[r][0] = R[0][r]; inv[r][1] = R[1][r]; inv[r][2] = R[2][r];
            inv[r][3] = -(R[0][r] * t[0] + R[1][r] * t[1] + R[2][r] * t[2]);
        }
        double K[3][3];
        for (int r = 0; r < 3; r++)
            for (int c = 0; c < 3; c++)
                K[r][c] = (double)intr[i * 9 + r * 3 + c];
        for (int c = 0; c < 3; c++) { K[0][c] *= (double)WW; K[1][c] *= (double)HH; }
        for (int r = 0; r < 3; r++)
            for (int c = 0; c < 4; c++) {
                double s = K[r][0] * inv[0][c] + K[r][1] * inv[1][c] + K[r][2] * inv[2][c];
                s_proj[i][r * 4 + c] = (float)s;
            }
        for (int c = 0; c < 4; c++) s_row2[i][c] = (float)inv[2][c];
    }
    __syncthreads();

    // ---- point path (point block index = grp) ----
    int n = grp * blockDim.x + threadIdx.x;

    int   b  = bids[n];
    float cf = conf[n];
    float2 p0 = reinterpret_cast<const float2*>(mk0)[n];
    float2 p1 = reinterpret_cast<const float2*>(mk1)[n];

    // prefetch random gathers; their DRAM latency hides under the Jacobi chain.
    int   pix0, pix1;
    float cost0, cost1;
    {
        int x0 = min(max((int)p0.x, 0), WW - 1);
        int y0 = min(max((int)p0.y, 0), HH - 1);
        pix0 = ((b * HH + y0) << 10) + x0;                      // v=0
        int x1 = min(max((int)p1.x, 0), WW - 1);
        int y1 = min(max((int)p1.y, 0), HH - 1);
        pix1 = (((BATCH + b) * HH + y1) << 10) + x1;            // v=1
        cost0 = __ldg(&disps[pix0]);
        cost1 = __ldg(&disps[pix1]);
    }

    const float* P0 = s_proj[b * 2 + 0];
    const float* P1 = s_proj[b * 2 + 1];

    float A[4][4];
#pragma unroll
    for (int k = 0; k < 4; k++) {
        A[0][k] = (P0[8 + k] * p0.x - P0[0 + k]) * cf;
        A[1][k] = (P0[8 + k] * p0.y - P0[4 + k]) * cf;
        A[2][k] = (P1[8 + k] * p1.x - P1[0 + k]) * cf;
        A[3][k] = (P1[8 + k] * p1.y - P1[4 + k]) * cf;
    }

    float M[4][4];
#pragma unroll
    for (int i = 0; i < 4; i++)
#pragma unroll
        for (int j = i; j < 4; j++) {
            float s = A[0][i] * A[0][j];
            s = fmaf(A[1][i], A[1][j], s);
            s = fmaf(A[2][i], A[2][j], s);
            s = fmaf(A[3][i], A[3][j], s);
            M[i][j] = s; M[j][i] = s;
        }

    // relative convergence threshold: eps * trace (trace is rotation-invariant)
    float thr = 1.1920929e-7f * (M[0][0] + M[1][1] + M[2][2] + M[3][3]);

    float Vv[4][4] = {{1,0,0,0},{0,1,0,0},{0,0,1,0},{0,0,0,1}};

#pragma unroll 1
    for (int sweep = 0; sweep < 8; sweep++) {
        jrot<0,1>(M, Vv, thr); jrot<0,2>(M, Vv, thr); jrot<0,3>(M, Vv, thr);
        jrot<1,2>(M, Vv, thr); jrot<1,3>(M, Vv, thr); jrot<2,3>(M, Vv, thr);
    }

    // min-eigenvalue column via static predicated selects (register-resident)
    float dm = M[0][0];
    float h0 = Vv[0][0], h1 = Vv[1][0], h2 = Vv[2][0], h3 = Vv[3][0];
#pragma unroll
    for (int j = 1; j < 4; j++) {
        bool lt = M[j][j] < dm;
        dm = lt ? M[j][j] : dm;
        h0 = lt ? Vv[0][j] : h0;
        h1 = lt ? Vv[1][j] : h1;
        h2 = lt ? Vv[2][j] : h2;
        h3 = lt ? Vv[3][j] : h3;
    }
    float px = h0 / h3, py = h1 / h3, pz = h2 / h3;

    const float* r20 = s_row2[b * 2 + 0];
    const float* r21 = s_row2[b * 2 + 1];
    float z0 = fmaf(r20[0], px, fmaf(r20[1], py, fmaf(r20[2], pz, r20[3])));
    float z1 = fmaf(r21[0], px, fmaf(r21[1], py, fmaf(r21[2], pz, r21[3])));

    bool valid = (z0 > 0.0f) && (z0 < 500.0f) && (z1 > 0.0f) && (z1 < 500.0f);

    // ---- warp-aggregated near/far/has reduction (the R14 win) -----------
    {
        unsigned anyv = __ballot_sync(0xffffffffu, valid);
        bool uni = __all_sync(0xffffffffu, __shfl_sync(0xffffffffu, b, 0) == b);
        if (uni) {
            float m0 = valid ? z0 : __int_as_float(0x7f800000);   // +inf
            float m1 = valid ? z1 : __int_as_float(0x7f800000);
            float M0 = valid ? z0 : 0.0f;
            float M1 = valid ? z1 : 0.0f;
#pragma unroll
            for (int o = 16; o > 0; o >>= 1) {
                m0 = fminf(m0, __shfl_xor_sync(0xffffffffu, m0, o));
                m1 = fminf(m1, __shfl_xor_sync(0xffffffffu, m1, o));
                M0 = fmaxf(M0, __shfl_xor_sync(0xffffffffu, M0, o));
                M1 = fmaxf(M1, __shfl_xor_sync(0xffffffffu, M1, o));
            }
            if ((threadIdx.x & 31) == 0 && anyv) {
                atomicMin(&g_near[b * 2 + 0], __float_as_uint(m0));
                atomicMin(&g_near[b * 2 + 1], __float_as_uint(m1));
                atomicMax(&g_far [b * 2 + 0], __float_as_uint(M0));
                atomicMax(&g_far [b * 2 + 1], __float_as_uint(M1));
                g_has[b] = 1;
            }
        } else if (valid) {
            atomicMin(&g_near[b * 2 + 0], __float_as_uint(z0));
            atomicMin(&g_near[b * 2 + 1], __float_as_uint(z1));
            atomicMax(&g_far [b * 2 + 0], __float_as_uint(z0));
            atomicMax(&g_far [b * 2 + 1], __float_as_uint(z1));
            g_has[b] = 1;
        }
    }

    {
        float val0 = valid ? (0.5f * (1.0f / z0) + 0.5f * cost0) : cost0;
        float val1 = valid ? (0.5f * (1.0f / z1) + 0.5f * cost1) : cost1;
        g_val[n * 2 + 0] = val0;
        g_val[n * 2 + 1] = val1;
        g_pix[n * 2 + 0] = pix0;
        g_pix[n * 2 + 1] = pix1;
        // winner decided HERE (no-return REDG, same cost class as the plain
        // clear-store it replaces) — deletes the separate winner_k pass.
        atomicMax(&g_winner[pix0], (unsigned)n + 1u);
        atomicMax(&g_winner[pix1], (unsigned)n + 1u);
    }
}

// ---------------- K2: scatter winners (+self-clean) + near/far/flag ---------
__global__ void scatter_final_k(float* __restrict__ out)
{
    int i = blockIdx.x * blockDim.x + threadIdx.x;
    if (i < NPTS * 2) {
        int pix = g_pix[i];
        unsigned w = g_winner[pix];
        if (w == (unsigned)(i >> 1) + 1u) {
            out[pix] = g_val[i];
            g_winner[pix] = 0u;            // restore all-zero invariant
        }
        // losers racing the reset see 0 or the max key — neither matches
        // their own key, so they never write: race-free.
    }
    if (blockIdx.x == 0 && threadIdx.x < BATCH * VIEWS) {
        int t = threadIdx.x;
        int has = g_has[t >> 1];
        out[FUSED_ELEMS +  0 + t] = has ? __uint_as_float(g_near[t]) : 0.0f;
        out[FUSED_ELEMS + 16 + t] = has ? __uint_as_float(g_far[t])  : 500.0f;
        out[FUSED_ELEMS + 32 + t] = has ? 1.0f : 0.0f;
        // restore reset-state invariant for the next graph replay.
        g_near[t] = 0x7f800000u;
        g_far[t]  = 0u;
        if (t < BATCH) g_has[t] = 0;
    }
}

// ---------------- launch -----------------------------------------------------
extern "C" void kernel_launch(void* const* d_in, const int* in_sizes, int n_in,
                              void* d_out, int out_size)
{
    const float* mk0   = (const float*)d_in[0];
    const float* mk1   = (const float*)d_in[1];
    const float* conf  = (const float*)d_in[2];
    const int*   bids  = (const int*)  d_in[3];
    const float* intr  = (const float*)d_in[4];
    const float* extr  = (const float*)d_in[5];
    const float* disps = (const float*)d_in[6];
    float* out = (float*)d_out;

    fused_k        <<<TOT_BLOCKS, 256>>>(mk0, mk1, conf, bids, intr, extr, disps, out);
    scatter_final_k<<<(NPTS * 2) / 256, 256>>>(out);
}

// round 16
// speedup vs baseline: 1.2073x; 1.2073x over previous
#include <cuda_runtime.h>
#include <math.h>

#define NPTS   131072
#define BATCH  8
#define VIEWS  2
#define HH     1024
#define WW     1024
#define NPIX   (VIEWS * BATCH * HH * WW)   // 16777216
#define FUSED_ELEMS NPIX

#define PT_BLOCKS   (NPTS / 256)           // 512
#define CP_BLOCKS   4096                   // each thread copies 4 float4
#define CP_THREADS  (CP_BLOCKS * 256)      // 1048576

// ---------------- scratch (device globals only; no allocation allowed) ------
__device__ unsigned int g_near[BATCH * VIEWS] = {
    0x7f800000u,0x7f800000u,0x7f800000u,0x7f800000u,
    0x7f800000u,0x7f800000u,0x7f800000u,0x7f800000u,
    0x7f800000u,0x7f800000u,0x7f800000u,0x7f800000u,
    0x7f800000u,0x7f800000u,0x7f800000u,0x7f800000u};
__device__ unsigned int g_far[BATCH * VIEWS]  = {0};
__device__ int          g_has[BATCH]          = {0};
// Self-cleaning winner map: 0 == clean (zero-init at load; scatter_final_k
// re-zeroes exactly the entries each replay dirties). Key = point index n + 1;
// contenders at a pixel have distinct n, so atomicMax picks the reference's
// last-write-wins point deterministically. (Protocol validated in R15.)
__device__ unsigned int g_winner[NPIX];             // 64 MB
__device__ float        g_val[NPTS * 2];
__device__ int          g_pix[NPTS * 2];

// ---------------- Jacobi rotation on 4x4 symmetric, fixed (P,Q) -------------
// Executed path: EXACT IEEE sequence (best-known accuracy, rel_err 7.945e-4).
// Relative skip threshold (eps*trace) — converged rotations skip instead of
// burning MUFU on rounding noise.
template <int P, int Q>
__device__ __forceinline__ void jrot(float M[4][4], float Vv[4][4], float thr)
{
    float apq = M[P][Q];
    if (fabsf(apq) < thr) return;
    float app = M[P][P], aqq = M[Q][Q];
    float tau = (aqq - app) / (2.0f * apq);
    float t = copysignf(1.0f, tau) / (fabsf(tau) + sqrtf(1.0f + tau * tau));
    float c = 1.0f / sqrtf(1.0f + t * t);
    float s = t * c;
    M[P][P] = app - t * apq;
    M[Q][Q] = aqq + t * apq;
    M[P][Q] = 0.0f; M[Q][P] = 0.0f;
#pragma unroll
    for (int k = 0; k < 4; k++) {
        if (k == P || k == Q) continue;
        float mkp = M[k][P], mkq = M[k][Q];
        float np = c * mkp - s * mkq;
        float nq = s * mkp + c * mkq;
        M[k][P] = np; M[P][k] = np;
        M[k][Q] = nq; M[Q][k] = nq;
    }
#pragma unroll
    for (int k = 0; k < 4; k++) {
        float vkp = Vv[k][P], vkq = Vv[k][Q];
        Vv[k][P] = c * vkp - s * vkq;
        Vv[k][Q] = s * vkp + c * vkq;
    }
}

// ---------------- K1 (fused): point blocks FIRST, then copy blocks ----------
// R14 layout restored: point blocks occupy blockIdx 0-511 so ALL of them start
// in wave 1 and run concurrently with the streaming copy for the whole kernel.
// (R15's interleave spread them across waves — late-wave point blocks became
// 20-40us stragglers serialized after the copy: 42 -> 56us. A point block's
// lifetime is comparable to the entire kernel; it must launch in wave 1.)
__global__ void fused_k(const float* __restrict__ mk0,
                        const float* __restrict__ mk1,
                        const float* __restrict__ conf,
                        const int*   __restrict__ bids,
                        const float* __restrict__ intr,
                        const float* __restrict__ extr,
                        const float* __restrict__ disps,
                        float*       __restrict__ out)
{
    if (blockIdx.x >= PT_BLOCKS) {
        // ---- copy path ----
        const float4* in4  = (const float4*)disps;
        float4*       out4 = (float4*)out;
        int i = (blockIdx.x - PT_BLOCKS) * blockDim.x + threadIdx.x;
#pragma unroll
        for (int j = 0; j < 4; j++)
            out4[i + j * CP_THREADS] = in4[i + j * CP_THREADS];
        return;
    }

    // ---- per-block setup: 16 (b,v) projection matrices into SMEM ----
    __shared__ float s_proj[BATCH * VIEWS][12];
    __shared__ float s_row2[BATCH * VIEWS][4];
    if (threadIdx.x < BATCH * VIEWS) {
        int i = threadIdx.x;
        // extrinsics are rigid: E = [R t; 0 0 0 1]  =>  inv = [R^T, -R^T t; 0 1]
        double R[3][3], t[3];
        for (int r = 0; r < 3; r++) {
            for (int c = 0; c < 3; c++) R[r][c] = (double)extr[i * 16 + r * 4 + c];
            t[r] = (double)extr[i * 16 + r * 4 + 3];
        }
        double inv[3][4];
        for (int r = 0; r < 3; r++) {
            inv[r][0] = R[0][r]; inv[r][1] = R[1][r]; inv[r][2] = R[2][r];
            inv[r][3] = -(R[0][r] * t[0] + R[1][r] * t[1] + R[2][r] * t[2]);
        }
        double K[3][3];
        for (int r = 0; r < 3; r++)
            for (int c = 0; c < 3; c++)
                K[r][c] = (double)intr[i * 9 + r * 3 + c];
        for (int c = 0; c < 3; c++) { K[0][c] *= (double)WW; K[1][c] *= (double)HH; }
        for (int r = 0; r < 3; r++)
            for (int c = 0; c < 4; c++) {
                double s = K[r][0] * inv[0][c] + K[r][1] * inv[1][c] + K[r][2] * inv[2][c];
                s_proj[i][r * 4 + c] = (float)s;
            }
        for (int c = 0; c < 4; c++) s_row2[i][c] = (float)inv[2][c];
    }
    __syncthreads();

    // ---- point path ----
    int n = blockIdx.x * blockDim.x + threadIdx.x;

    int   b  = bids[n];
    float cf = conf[n];
    float2 p0 = reinterpret_cast<const float2*>(mk0)[n];
    float2 p1 = reinterpret_cast<const float2*>(mk1)[n];

    // prefetch random gathers; their DRAM latency hides under the Jacobi chain.
    int   pix0, pix1;
    float cost0, cost1;
    {
        int x0 = min(max((int)p0.x, 0), WW - 1);
        int y0 = min(max((int)p0.y, 0), HH - 1);
        pix0 = ((b * HH + y0) << 10) + x0;                      // v=0
        int x1 = min(max((int)p1.x, 0), WW - 1);
        int y1 = min(max((int)p1.y, 0), HH - 1);
        pix1 = (((BATCH + b) * HH + y1) << 10) + x1;            // v=1
        cost0 = __ldg(&disps[pix0]);
        cost1 = __ldg(&disps[pix1]);
    }

    const float* P0 = s_proj[b * 2 + 0];
    const float* P1 = s_proj[b * 2 + 1];

    float A[4][4];
#pragma unroll
    for (int k = 0; k < 4; k++) {
        A[0][k] = (P0[8 + k] * p0.x - P0[0 + k]) * cf;
        A[1][k] = (P0[8 + k] * p0.y - P0[4 + k]) * cf;
        A[2][k] = (P1[8 + k] * p1.x - P1[0 + k]) * cf;
        A[3][k] = (P1[8 + k] * p1.y - P1[4 + k]) * cf;
    }

    float M[4][4];
#pragma unroll
    for (int i = 0; i < 4; i++)
#pragma unroll
        for (int j = i; j < 4; j++) {
            float s = A[0][i] * A[0][j];
            s = fmaf(A[1][i], A[1][j], s);
            s = fmaf(A[2][i], A[2][j], s);
            s = fmaf(A[3][i], A[3][j], s);
            M[i][j] = s; M[j][i] = s;
        }

    // relative convergence threshold: eps * trace (trace is rotation-invariant)
    float thr = 1.1920929e-7f * (M[0][0] + M[1][1] + M[2][2] + M[3][3]);

    float Vv[4][4] = {{1,0,0,0},{0,1,0,0},{0,0,1,0},{0,0,0,1}};

#pragma unroll 1
    for (int sweep = 0; sweep < 8; sweep++) {
        jrot<0,1>(M, Vv, thr); jrot<0,2>(M, Vv, thr); jrot<0,3>(M, Vv, thr);
        jrot<1,2>(M, Vv, thr); jrot<1,3>(M, Vv, thr); jrot<2,3>(M, Vv, thr);
    }

    // min-eigenvalue column via static predicated selects (register-resident)
    float dm = M[0][0];
    float h0 = Vv[0][0], h1 = Vv[1][0], h2 = Vv[2][0], h3 = Vv[3][0];
#pragma unroll
    for (int j = 1; j < 4; j++) {
        bool lt = M[j][j] < dm;
        dm = lt ? M[j][j] : dm;
        h0 = lt ? Vv[0][j] : h0;
        h1 = lt ? Vv[1][j] : h1;
        h2 = lt ? Vv[2][j] : h2;
        h3 = lt ? Vv[3][j] : h3;
    }
    float px = h0 / h3, py = h1 / h3, pz = h2 / h3;

    const float* r20 = s_row2[b * 2 + 0];
    const float* r21 = s_row2[b * 2 + 1];
    float z0 = fmaf(r20[0], px, fmaf(r20[1], py, fmaf(r20[2], pz, r20[3])));
    float z1 = fmaf(r21[0], px, fmaf(r21[1], py, fmaf(r21[2], pz, r21[3])));

    bool valid = (z0 > 0.0f) && (z0 < 500.0f) && (z1 > 0.0f) && (z1 < 500.0f);

    // ---- warp-aggregated near/far/has reduction (the R14 win) -----------
    {
        unsigned anyv = __ballot_sync(0xffffffffu, valid);
        bool uni = __all_sync(0xffffffffu, __shfl_sync(0xffffffffu, b, 0) == b);
        if (uni) {
            float m0 = valid ? z0 : __int_as_float(0x7f800000);   // +inf
            float m1 = valid ? z1 : __int_as_float(0x7f800000);
            float M0 = valid ? z0 : 0.0f;
            float M1 = valid ? z1 : 0.0f;
#pragma unroll
            for (int o = 16; o > 0; o >>= 1) {
                m0 = fminf(m0, __shfl_xor_sync(0xffffffffu, m0, o));
                m1 = fminf(m1, __shfl_xor_sync(0xffffffffu, m1, o));
                M0 = fmaxf(M0, __shfl_xor_sync(0xffffffffu, M0, o));
                M1 = fmaxf(M1, __shfl_xor_sync(0xffffffffu, M1, o));
            }
            if ((threadIdx.x & 31) == 0 && anyv) {
                atomicMin(&g_near[b * 2 + 0], __float_as_uint(m0));
                atomicMin(&g_near[b * 2 + 1], __float_as_uint(m1));
                atomicMax(&g_far [b * 2 + 0], __float_as_uint(M0));
                atomicMax(&g_far [b * 2 + 1], __float_as_uint(M1));
                g_has[b] = 1;
            }
        } else if (valid) {
            atomicMin(&g_near[b * 2 + 0], __float_as_uint(z0));
            atomicMin(&g_near[b * 2 + 1], __float_as_uint(z1));
            atomicMax(&g_far [b * 2 + 0], __float_as_uint(z0));
            atomicMax(&g_far [b * 2 + 1], __float_as_uint(z1));
            g_has[b] = 1;
        }
    }

    {
        float val0 = valid ? (0.5f * (1.0f / z0) + 0.5f * cost0) : cost0;
        float val1 = valid ? (0.5f * (1.0f / z1) + 0.5f * cost1) : cost1;
        g_val[n * 2 + 0] = val0;
        g_val[n * 2 + 1] = val1;
        g_pix[n * 2 + 0] = pix0;
        g_pix[n * 2 + 1] = pix1;
        // winner decided here (no-return REDG, same cost class as the plain
        // clear-store it replaces) — the separate winner_k pass is deleted.
        atomicMax(&g_winner[pix0], (unsigned)n + 1u);
        atomicMax(&g_winner[pix1], (unsigned)n + 1u);
    }
}

// ---------------- K2: scatter winners (+self-clean) + near/far/flag ---------
__global__ void scatter_final_k(float* __restrict__ out)
{
    int i = blockIdx.x * blockDim.x + threadIdx.x;
    if (i < NPTS * 2) {
        int pix = g_pix[i];
        unsigned w = g_winner[pix];
        if (w == (unsigned)(i >> 1) + 1u) {
            out[pix] = g_val[i];
            g_winner[pix] = 0u;            // restore all-zero invariant
        }
        // losers racing the reset see 0 or the max key — neither matches
        // their own key, so they never write: race-free.
    }
    if (blockIdx.x == 0 && threadIdx.x < BATCH * VIEWS) {
        int t = threadIdx.x;
        int has = g_has[t >> 1];
        out[FUSED_ELEMS +  0 + t] = has ? __uint_as_float(g_near[t]) : 0.0f;
        out[FUSED_ELEMS + 16 + t] = has ? __uint_as_float(g_far[t])  : 500.0f;
        out[FUSED_ELEMS + 32 + t] = has ? 1.0f : 0.0f;
        // restore reset-state invariant for the next graph replay.
        g_near[t] = 0x7f800000u;
        g_far[t]  = 0u;
        if (t < BATCH) g_has[t] = 0;
    }
}

// ---------------- launch -----------------------------------------------------
extern "C" void kernel_launch(void* const* d_in, const int* in_sizes, int n_in,
                              void* d_out, int out_size)
{
    const float* mk0   = (const float*)d_in[0];
    const float* mk1   = (const float*)d_in[1];
    const float* conf  = (const float*)d_in[2];
    const int*   bids  = (const int*)  d_in[3];
    const float* intr  = (const float*)d_in[4];
    const float* extr  = (const float*)d_in[5];
    const float* disps = (const float*)d_in[6];
    float* out = (float*)d_out;

    fused_k        <<<PT_BLOCKS + CP_BLOCKS, 256>>>(mk0, mk1, conf, bids, intr, extr, disps, out);
    scatter_final_k<<<(NPTS * 2) / 256, 256>>>(out);
}